// round 4
// baseline (speedup 1.0000x reference)
#include <cuda_runtime.h>
#include <cuda_bf16.h>

#define NCLS 54
#define RPB  192
#define THREADS 192

// -log(1 - 53*0.001) = -log(0.947)
#define C0_TERM 0.05445614f

__device__ double g_acc;           // zero-initialized at module load; reset by last block
__device__ unsigned int g_done;

__global__ void __launch_bounds__(THREADS)
importance_loss_fused(const float* __restrict__ logits,
                      const int*   __restrict__ target,
                      const int*   __restrict__ mask,   // bool promoted to int32 by harness
                      float* __restrict__ out,
                      int batch, int nblocks)
{
    __shared__ float s[RPB * NCLS];          // 41472 B -> 5 blocks/SM
    __shared__ unsigned char smask[64];
    __shared__ float red[THREADS / 32];

    const int row0  = blockIdx.x * RPB;
    const int rows  = min(RPB, batch - row0);
    const int nflt  = rows * NCLS;

    // ---- stage logits chunk into smem, fully coalesced float4 ----
    const float* base = logits + (long long)row0 * NCLS;
    const int n4 = nflt >> 2;
    const float4* src4 = (const float4*)base;   // row0*54*4 = 41472*blk -> 16B aligned
    float4* s4 = (float4*)s;
    for (int i = threadIdx.x; i < n4; i += THREADS) s4[i] = src4[i];
    for (int i = (n4 << 2) + threadIdx.x; i < nflt; i += THREADS) s[i] = base[i];
    if (threadIdx.x < NCLS) smask[threadIdx.x] = (unsigned char)(mask[threadIdx.x] != 0);
    __syncthreads();

    // ---- one row per thread, two smem passes (no register array) ----
    float term = 0.0f;
    if (threadIdx.x < rows) {
        const float* x = s + threadIdx.x * NCLS;

        float m = -3.0e38f;
        int   am = 0;
        #pragma unroll
        for (int j = 0; j < NCLS; j++) {
            float v = x[j];
            if (v > m) { m = v; am = j; }        // strict '>' == first occurrence (jnp.argmax)
        }
        float sum = 0.0f;
        #pragma unroll
        for (int j = 0; j < NCLS; j++) sum += __expf(x[j] - m);

        const int t = target[row0 + threadIdx.x];
        const float xt = x[t];
        const bool keep = (smask[am] | smask[t]) != 0;
        const float lse = m + __logf(sum);
        term = keep ? (lse - xt) : C0_TERM;
    }

    // ---- block reduction ----
    #pragma unroll
    for (int o = 16; o > 0; o >>= 1)
        term += __shfl_down_sync(0xffffffffu, term, o);
    const int lane = threadIdx.x & 31;
    const int w    = threadIdx.x >> 5;
    if (lane == 0) red[w] = term;
    __syncthreads();

    if (threadIdx.x == 0) {
        float bs = 0.0f;
        #pragma unroll
        for (int i = 0; i < THREADS / 32; i++) bs += red[i];
        atomicAdd(&g_acc, (double)bs);
        __threadfence();
        unsigned int done = atomicAdd(&g_done, 1u);
        if (done == (unsigned int)(nblocks - 1)) {
            // last block: all other blocks' atomicAdds are visible (L2-coherent)
            double total = atomicAdd(&g_acc, 0.0);   // atomic read, bypasses L1
            out[0] = (float)(total / (double)batch);
            g_acc  = 0.0;                             // reset for next graph replay
            g_done = 0u;
        }
    }
}

extern "C" void kernel_launch(void* const* d_in, const int* in_sizes, int n_in,
                              void* d_out, int out_size)
{
    const float* logits = (const float*)d_in[0];
    const int*   target = (const int*)d_in[1];
    const int*   mask   = (const int*)d_in[2];
    float* out = (float*)d_out;

    const int batch  = in_sizes[1];          // element count of target == B
    const int blocks = (batch + RPB - 1) / RPB;

    importance_loss_fused<<<blocks, THREADS>>>(logits, target, mask, out, batch, blocks);
}

// round 5
// speedup vs baseline: 1.4572x; 1.4572x over previous
#include <cuda_runtime.h>
#include <cuda_bf16.h>
#include <cstdint>

#define NCLS 54
#define RPB  192
#define THREADS 192

// -log(1 - 53*0.001) = -log(0.947)
#define C0_TERM 0.05445614f

__device__ double g_acc;           // module-load zeroed; reset by last block each run
__device__ unsigned int g_done;

__device__ __forceinline__ uint32_t smem_u32(const void* p) {
    return (uint32_t)__cvta_generic_to_shared(p);
}

__global__ void __launch_bounds__(THREADS, 5)
importance_loss_tma(const float* __restrict__ logits,
                    const int*   __restrict__ target,
                    const int*   __restrict__ mask,    // bool promoted to int32
                    float* __restrict__ out,
                    int batch, int nblocks)
{
    __shared__ float s[RPB * NCLS];                    // 41472 B
    __shared__ unsigned char smask[64];
    __shared__ float red[THREADS / 32];
    __shared__ __align__(8) unsigned long long mbar;

    const int tid  = threadIdx.x;
    const int row0 = blockIdx.x * RPB;
    const int rows = min(RPB, batch - row0);
    const int nbytes = rows * NCLS * 4;
    const int nmain  = nbytes & ~15;                   // bulk-copy needs 16B multiple

    if (tid == 0)
        asm volatile("mbarrier.init.shared.b64 [%0], 1;"
                     :: "r"(smem_u32(&mbar)) : "memory");
    __syncthreads();

    const char* src = (const char*)(logits + (long long)row0 * NCLS); // 41472*blk -> 16B aligned
    if (tid == 0) {
        asm volatile("mbarrier.arrive.expect_tx.shared.b64 _, [%0], %1;"
                     :: "r"(smem_u32(&mbar)), "r"((uint32_t)nmain) : "memory");
        asm volatile("cp.async.bulk.shared::cta.global.mbarrier::complete_tx::bytes "
                     "[%0], [%1], %2, [%3];"
                     :: "r"(smem_u32(s)), "l"(src), "r"((uint32_t)nmain),
                        "r"(smem_u32(&mbar)) : "memory");
        for (int b = nmain; b < nbytes; b += 4)        // <16B tail (unused for this shape)
            *(float*)((char*)s + b) = *(const float*)(src + b);
    }
    if (tid < NCLS) smask[tid] = (unsigned char)(mask[tid] != 0);

    // overlap target load with the TMA copy
    int t = 0;
    if (tid < rows) t = target[row0 + tid];

    // wait for bulk copy (phase 0), acquire semantics
    {
        uint32_t mba = smem_u32(&mbar);
        uint32_t done;
        asm volatile("{\n\t.reg .pred p;\n\t"
                     "mbarrier.try_wait.parity.acquire.cta.shared::cta.b64 p, [%1], 0;\n\t"
                     "selp.b32 %0, 1, 0, p;\n\t}"
                     : "=r"(done) : "r"(mba) : "memory");
        if (!done) {
            asm volatile("{\n\t.reg .pred P1;\n\t"
                         "WL_%=:\n\t"
                         "mbarrier.try_wait.parity.acquire.cta.shared::cta.b64 P1, [%0], 0, 0x989680;\n\t"
                         "@P1 bra.uni WD_%=;\n\t"
                         "bra.uni WL_%=;\n\t"
                         "WD_%=:\n\t}"
                         :: "r"(mba) : "memory");
        }
    }
    __syncthreads();   // covers t0's tail STS + smask stores for all threads

    // ---- one row per thread; conflict-free LDS.64, two passes, 4-way ILP ----
    float term = 0.0f;
    if (tid < rows) {
        const float2* x2 = (const float2*)(s + tid * NCLS);  // 216B stride, 8B aligned

        // pass 1: max via 4 independent fmaxf chains
        float m0 = -3.0e38f, m1 = -3.0e38f, m2 = -3.0e38f, m3 = -3.0e38f;
        #pragma unroll 9
        for (int k = 0; k < NCLS / 2; k++) {
            float2 v = x2[k];
            if (k & 1) { m2 = fmaxf(m2, v.x); m3 = fmaxf(m3, v.y); }
            else       { m0 = fmaxf(m0, v.x); m1 = fmaxf(m1, v.y); }
        }
        const float m = fmaxf(fmaxf(m0, m1), fmaxf(m2, m3));

        // pass 2: exp-sum (4 accumulators) + argmax as min index where x==m
        float s0 = 0.f, s1 = 0.f, s2 = 0.f, s3 = 0.f;
        int i0 = NCLS, i1 = NCLS;
        #pragma unroll 9
        for (int k = 0; k < NCLS / 2; k++) {
            float2 v = x2[k];
            if (k & 1) { s2 += __expf(v.x - m); s3 += __expf(v.y - m); }
            else       { s0 += __expf(v.x - m); s1 += __expf(v.y - m); }
            i0 = min(i0, (v.x == m) ? 2 * k     : NCLS);
            i1 = min(i1, (v.y == m) ? 2 * k + 1 : NCLS);
        }
        const float sum = (s0 + s1) + (s2 + s3);
        const int   am  = min(i0, i1);                 // first occurrence of the max

        const float xt  = s[tid * NCLS + t];
        const bool keep = (smask[am] | smask[t]) != 0;
        term = keep ? (m + __logf(sum) - xt) : C0_TERM;
    }

    // ---- block reduction ----
    #pragma unroll
    for (int o = 16; o > 0; o >>= 1)
        term += __shfl_down_sync(0xffffffffu, term, o);
    const int lane = tid & 31;
    const int w    = tid >> 5;
    if (lane == 0) red[w] = term;
    __syncthreads();

    if (tid == 0) {
        float bs = 0.0f;
        #pragma unroll
        for (int i = 0; i < THREADS / 32; i++) bs += red[i];
        atomicAdd(&g_acc, (double)bs);
        __threadfence();
        unsigned int done = atomicAdd(&g_done, 1u);
        if (done == (unsigned int)(nblocks - 1)) {
            double total = atomicAdd(&g_acc, 0.0);     // atomic read via L2
            out[0] = (float)(total / (double)batch);
            g_acc  = 0.0;                              // reset for next graph replay
            g_done = 0u;
        }
    }
}

extern "C" void kernel_launch(void* const* d_in, const int* in_sizes, int n_in,
                              void* d_out, int out_size)
{
    const float* logits = (const float*)d_in[0];
    const int*   target = (const int*)d_in[1];
    const int*   mask   = (const int*)d_in[2];
    float* out = (float*)d_out;

    const int batch  = in_sizes[1];
    const int blocks = (batch + RPB - 1) / RPB;

    importance_loss_tma<<<blocks, THREADS>>>(logits, target, mask, out, batch, blocks);
}